// round 4
// baseline (speedup 1.0000x reference)
#include <cuda_runtime.h>
#include <math.h>

// Problem constants
#define TOK   16384      // B*N = 4*4096
#define DM    2048       // d_model
#define HD    256        // H
#define NBG   32         // B*G
#define NPG   512        // tokens per group
#define EPS   1e-5f

// ---------------------------------------------------------------------------
// Scratch (device globals; no allocations allowed)
// ---------------------------------------------------------------------------
__device__ float g_q[TOK * HD];     // q (raw -> normalized)
__device__ float g_k[TOK * HD];     // k (raw -> normalized)
__device__ float g_v[TOK * HD];     // v (raw -> layernormed -> surprise, in place)
__device__ float g_of[TOK * HD];    // out_f = q @ M_next^T
__device__ float g_gamma[NBG];      // per-(b,g) gate

// ---------------------------------------------------------------------------
// Block-wide sum over 256 threads (8 warps)
// ---------------------------------------------------------------------------
__device__ __forceinline__ float blockSum256(float v) {
    __shared__ float red[8];
    #pragma unroll
    for (int o = 16; o > 0; o >>= 1) v += __shfl_xor_sync(0xffffffffu, v, o);
    if ((threadIdx.x & 31) == 0) red[threadIdx.x >> 5] = v;
    __syncthreads();
    float s = red[0] + red[1] + red[2] + red[3] + red[4] + red[5] + red[6] + red[7];
    __syncthreads();   // protect red[] for next call
    return s;
}

// ---------------------------------------------------------------------------
// Kernel 1: fused QKV GEMM.  C = x @ W + b for W in {Wq,Wk,Wv}
// Classic 128x128x8 fp32 SGEMM, 256 threads, 8x8 per-thread microtile.
// grid: x = 6 column tiles (2 per weight), y = 128 row tiles.
// ---------------------------------------------------------------------------
__global__ __launch_bounds__(256) void k_qkv(
    const float* __restrict__ x,
    const float* __restrict__ Wq, const float* __restrict__ bq,
    const float* __restrict__ Wk, const float* __restrict__ bk,
    const float* __restrict__ Wv, const float* __restrict__ bv)
{
    const int which = blockIdx.x >> 1;
    const float* __restrict__ W    = (which == 0) ? Wq : (which == 1) ? Wk : Wv;
    const float* __restrict__ bias = (which == 0) ? bq : (which == 1) ? bk : bv;
    float* __restrict__ C          = (which == 0) ? g_q : (which == 1) ? g_k : g_v;

    const int n0 = (blockIdx.x & 1) * 128;
    const int m0 = blockIdx.y * 128;

    __shared__ float As[8][128];
    __shared__ float Bs[8][128];

    const int tid  = threadIdx.x;
    const int tx   = tid & 15, ty = tid >> 4;
    const int arow = tid >> 1, acol = (tid & 1) * 4;
    const int brow = tid >> 5, bcol = (tid & 31) * 4;

    const float* Ap = x + (size_t)(m0 + arow) * DM + acol;
    const float* Bp = W + (size_t)brow * HD + n0 + bcol;

    float acc[8][8];
    #pragma unroll
    for (int i = 0; i < 8; i++)
        #pragma unroll
        for (int j = 0; j < 8; j++) acc[i][j] = 0.f;

    for (int k0 = 0; k0 < DM; k0 += 8) {
        float4 a = *(const float4*)(Ap + k0);
        As[acol + 0][arow] = a.x; As[acol + 1][arow] = a.y;
        As[acol + 2][arow] = a.z; As[acol + 3][arow] = a.w;
        *(float4*)&Bs[brow][bcol] = *(const float4*)(Bp + (size_t)k0 * HD);
        __syncthreads();
        #pragma unroll
        for (int kk = 0; kk < 8; kk++) {
            float ra[8], rb[8];
            *(float4*)&ra[0] = *(const float4*)&As[kk][ty * 8];
            *(float4*)&ra[4] = *(const float4*)&As[kk][ty * 8 + 4];
            *(float4*)&rb[0] = *(const float4*)&Bs[kk][tx * 8];
            *(float4*)&rb[4] = *(const float4*)&Bs[kk][tx * 8 + 4];
            #pragma unroll
            for (int i = 0; i < 8; i++)
                #pragma unroll
                for (int j = 0; j < 8; j++)
                    acc[i][j] = fmaf(ra[i], rb[j], acc[i][j]);
        }
        __syncthreads();
    }

    #pragma unroll
    for (int i = 0; i < 8; i++) {
        const int row = m0 + ty * 8 + i;
        #pragma unroll
        for (int j = 0; j < 8; j += 4) {
            const int col = n0 + tx * 8 + j;
            float4 o;
            o.x = acc[i][j + 0] + bias[col + 0];
            o.y = acc[i][j + 1] + bias[col + 1];
            o.z = acc[i][j + 2] + bias[col + 2];
            o.w = acc[i][j + 3] + bias[col + 3];
            *(float4*)&C[(size_t)row * HD + col] = o;
        }
    }
}

// ---------------------------------------------------------------------------
// Kernel 2: gamma. One block per (b,g) group.
// gamma[bg] = sigmoid( mean_n (x[bg] @ Wd) + bd + timescale[g] )
// ---------------------------------------------------------------------------
__global__ __launch_bounds__(256) void k_gamma(
    const float* __restrict__ x, const float* __restrict__ Wd,
    const float* __restrict__ bd, const float* __restrict__ ts)
{
    const int bg = blockIdx.x;
    const float* xr = x + (size_t)bg * NPG * DM;
    float acc = 0.f;
    for (int n = 0; n < NPG; n++) {
        const float* row = xr + (size_t)n * DM;
        for (int c = threadIdx.x; c < DM; c += 256)
            acc = fmaf(row[c], Wd[c], acc);
    }
    float s = blockSum256(acc);
    if (threadIdx.x == 0) {
        float z = s * (1.f / NPG) + bd[0] + ts[bg & 7];
        g_gamma[bg] = 1.f / (1.f + expf(-z));
    }
}

// ---------------------------------------------------------------------------
// Kernel 3: row normalization. One block (256 thr) per token row.
// q,k: x / max(||x||, eps).   v: layernorm.
// ---------------------------------------------------------------------------
__global__ __launch_bounds__(256) void k_norm(
    const float* __restrict__ ln_g, const float* __restrict__ ln_b)
{
    const int r = blockIdx.x, t = threadIdx.x;
    const size_t idx = (size_t)r * HD + t;

    float qv = g_q[idx];
    float s = blockSum256(qv * qv);
    g_q[idx] = qv / fmaxf(sqrtf(s), EPS);

    float kv = g_k[idx];
    s = blockSum256(kv * kv);
    g_k[idx] = kv / fmaxf(sqrtf(s), EPS);

    float vv = g_v[idx];
    float mu = blockSum256(vv) * (1.f / HD);
    float d = vv - mu;
    float var = blockSum256(d * d) * (1.f / HD);
    g_v[idx] = d * rsqrtf(var + EPS) * ln_g[t] + ln_b[t];
}

// ---------------------------------------------------------------------------
// Kernel 4/6: batched NT GEMM per group.  C[n,m] = A[n,:] . Bm[m,:]
//   mode 0: A = g_k, C = g_v in place:  surprise = v - k @ M_prev^T
//   mode 1: A = g_q, C = g_of:          out_f    = q @ M_next^T
// grid: (2 n-tiles, 4 m-tiles(rows of 512), 32 groups)
// ---------------------------------------------------------------------------
__global__ __launch_bounds__(256) void k_nt(const float* __restrict__ Bbase, int mode)
{
    const int bg = blockIdx.z;
    const float* __restrict__ A  = (mode == 0 ? g_k : g_q) + (size_t)bg * NPG * HD;
    const float* __restrict__ Bm = Bbase + (size_t)bg * HD * HD;
    float* __restrict__ C        = (mode == 0 ? g_v : g_of) + (size_t)bg * NPG * HD;

    const int n0 = blockIdx.x * 128;   // m-feature (columns of C)
    const int m0 = blockIdx.y * 128;   // token rows

    __shared__ float As[8][128];
    __shared__ float Bs[8][128];

    const int tid  = threadIdx.x;
    const int tx   = tid & 15, ty = tid >> 4;
    const int arow = tid >> 1, acol = (tid & 1) * 4;

    const float* Ap = A  + (size_t)(m0 + arow) * HD + acol;
    const float* Bp = Bm + (size_t)(n0 + arow) * HD + acol;

    float acc[8][8];
    #pragma unroll
    for (int i = 0; i < 8; i++)
        #pragma unroll
        for (int j = 0; j < 8; j++) acc[i][j] = 0.f;

    for (int k0 = 0; k0 < HD; k0 += 8) {
        float4 a = *(const float4*)(Ap + k0);
        As[acol + 0][arow] = a.x; As[acol + 1][arow] = a.y;
        As[acol + 2][arow] = a.z; As[acol + 3][arow] = a.w;
        float4 b = *(const float4*)(Bp + k0);
        Bs[acol + 0][arow] = b.x; Bs[acol + 1][arow] = b.y;
        Bs[acol + 2][arow] = b.z; Bs[acol + 3][arow] = b.w;
        __syncthreads();
        #pragma unroll
        for (int kk = 0; kk < 8; kk++) {
            float ra[8], rb[8];
            *(float4*)&ra[0] = *(const float4*)&As[kk][ty * 8];
            *(float4*)&ra[4] = *(const float4*)&As[kk][ty * 8 + 4];
            *(float4*)&rb[0] = *(const float4*)&Bs[kk][tx * 8];
            *(float4*)&rb[4] = *(const float4*)&Bs[kk][tx * 8 + 4];
            #pragma unroll
            for (int i = 0; i < 8; i++)
                #pragma unroll
                for (int j = 0; j < 8; j++)
                    acc[i][j] = fmaf(ra[i], rb[j], acc[i][j]);
        }
        __syncthreads();
    }

    #pragma unroll
    for (int i = 0; i < 8; i++) {
        const int row = m0 + ty * 8 + i;
        #pragma unroll
        for (int j = 0; j < 8; j++) {
            const size_t idx = (size_t)row * HD + n0 + tx * 8 + j;
            C[idx] = (mode == 0) ? (C[idx] - acc[i][j]) : acc[i][j];
        }
    }
}

// ---------------------------------------------------------------------------
// Kernel 5: TN GEMM + M_next epilogue, per group.
//   delta[m,h] = sum_n surprise[n,m] * k[n,h] / NPG
//   M_next = clip(gamma*M_prev + delta, -10, 10)  -> written into d_out tail
// grid: (2 h-tiles, 2 m-tiles, 32 groups)
// ---------------------------------------------------------------------------
__global__ __launch_bounds__(256) void k_tn_mnext(
    const float* __restrict__ Mprev, float* __restrict__ Mnext)
{
    const int bg = blockIdx.z;
    const float* __restrict__ A  = g_v + (size_t)bg * NPG * HD;  // surprise
    const float* __restrict__ Bm = g_k + (size_t)bg * NPG * HD;  // k

    const int h0 = blockIdx.x * 128;
    const int m0 = blockIdx.y * 128;

    __shared__ float As[8][128];
    __shared__ float Bs[8][128];

    const int tid  = threadIdx.x;
    const int tx   = tid & 15, ty = tid >> 4;
    const int krow = tid >> 5, kcol = (tid & 31) * 4;

    float acc[8][8];
    #pragma unroll
    for (int i = 0; i < 8; i++)
        #pragma unroll
        for (int j = 0; j < 8; j++) acc[i][j] = 0.f;

    for (int k0 = 0; k0 < NPG; k0 += 8) {
        *(float4*)&As[krow][kcol] = *(const float4*)&A [(size_t)(k0 + krow) * HD + m0 + kcol];
        *(float4*)&Bs[krow][kcol] = *(const float4*)&Bm[(size_t)(k0 + krow) * HD + h0 + kcol];
        __syncthreads();
        #pragma unroll
        for (int kk = 0; kk < 8; kk++) {
            float ra[8], rb[8];
            *(float4*)&ra[0] = *(const float4*)&As[kk][ty * 8];
            *(float4*)&ra[4] = *(const float4*)&As[kk][ty * 8 + 4];
            *(float4*)&rb[0] = *(const float4*)&Bs[kk][tx * 8];
            *(float4*)&rb[4] = *(const float4*)&Bs[kk][tx * 8 + 4];
            #pragma unroll
            for (int i = 0; i < 8; i++)
                #pragma unroll
                for (int j = 0; j < 8; j++)
                    acc[i][j] = fmaf(ra[i], rb[j], acc[i][j]);
        }
        __syncthreads();
    }

    const float g = g_gamma[bg];
    #pragma unroll
    for (int i = 0; i < 8; i++) {
        const int m = m0 + ty * 8 + i;
        #pragma unroll
        for (int j = 0; j < 8; j++) {
            const int h = h0 + tx * 8 + j;
            const size_t idx = (size_t)bg * HD * HD + (size_t)m * HD + h;
            float val = g * Mprev[idx] + acc[i][j] * (1.f / NPG);
            Mnext[idx] = fminf(fmaxf(val, -10.f), 10.f);
        }
    }
}

// ---------------------------------------------------------------------------
// Kernel 7: final GEMM.  out = out_f @ Wo + bo   [16384x256]x[256x2048]
// grid: (16 n-tiles, 128 m-tiles)
// ---------------------------------------------------------------------------
__global__ __launch_bounds__(256) void k_out(
    const float* __restrict__ Wo, const float* __restrict__ bo,
    float* __restrict__ out)
{
    const int n0 = blockIdx.x * 128;
    const int m0 = blockIdx.y * 128;

    __shared__ float As[8][128];
    __shared__ float Bs[8][128];

    const int tid  = threadIdx.x;
    const int tx   = tid & 15, ty = tid >> 4;
    const int arow = tid >> 1, acol = (tid & 1) * 4;
    const int brow = tid >> 5, bcol = (tid & 31) * 4;

    const float* Ap = g_of + (size_t)(m0 + arow) * HD + acol;
    const float* Bp = Wo + (size_t)brow * DM + n0 + bcol;

    float acc[8][8];
    #pragma unroll
    for (int i = 0; i < 8; i++)
        #pragma unroll
        for (int j = 0; j < 8; j++) acc[i][j] = 0.f;

    for (int k0 = 0; k0 < HD; k0 += 8) {
        float4 a = *(const float4*)(Ap + k0);
        As[acol + 0][arow] = a.x; As[acol + 1][arow] = a.y;
        As[acol + 2][arow] = a.z; As[acol + 3][arow] = a.w;
        *(float4*)&Bs[brow][bcol] = *(const float4*)(Bp + (size_t)k0 * DM);
        __syncthreads();
        #pragma unroll
        for (int kk = 0; kk < 8; kk++) {
            float ra[8], rb[8];
            *(float4*)&ra[0] = *(const float4*)&As[kk][ty * 8];
            *(float4*)&ra[4] = *(const float4*)&As[kk][ty * 8 + 4];
            *(float4*)&rb[0] = *(const float4*)&Bs[kk][tx * 8];
            *(float4*)&rb[4] = *(const float4*)&Bs[kk][tx * 8 + 4];
            #pragma unroll
            for (int i = 0; i < 8; i++)
                #pragma unroll
                for (int j = 0; j < 8; j++)
                    acc[i][j] = fmaf(ra[i], rb[j], acc[i][j]);
        }
        __syncthreads();
    }

    #pragma unroll
    for (int i = 0; i < 8; i++) {
        const int row = m0 + ty * 8 + i;
        #pragma unroll
        for (int j = 0; j < 8; j += 4) {
            const int col = n0 + tx * 8 + j;
            float4 o;
            o.x = acc[i][j + 0] + bo[col + 0];
            o.y = acc[i][j + 1] + bo[col + 1];
            o.z = acc[i][j + 2] + bo[col + 2];
            o.w = acc[i][j + 3] + bo[col + 3];
            *(float4*)&out[(size_t)row * DM + col] = o;
        }
    }
}

// ---------------------------------------------------------------------------
// Launch
// ---------------------------------------------------------------------------
extern "C" void kernel_launch(void* const* d_in, const int* in_sizes, int n_in,
                              void* d_out, int out_size)
{
    const float* x     = (const float*)d_in[0];
    const float* Mprev = (const float*)d_in[1];
    const float* Wq    = (const float*)d_in[2];
    const float* bq    = (const float*)d_in[3];
    const float* Wk    = (const float*)d_in[4];
    const float* bk    = (const float*)d_in[5];
    const float* Wv    = (const float*)d_in[6];
    const float* bv    = (const float*)d_in[7];
    const float* ln_g  = (const float*)d_in[8];
    const float* ln_b  = (const float*)d_in[9];
    const float* Wo    = (const float*)d_in[10];
    const float* bo    = (const float*)d_in[11];
    const float* Wd    = (const float*)d_in[12];
    const float* bd    = (const float*)d_in[13];
    const float* ts    = (const float*)d_in[14];

    float* out   = (float*)d_out;
    float* Mnext = out + (size_t)TOK * DM;   // second return value after `out`

    // 1) q,k,v raw projections
    k_qkv<<<dim3(6, 128), 256>>>(x, Wq, bq, Wk, bk, Wv, bv);
    // 2) gate gamma (independent of 1)
    k_gamma<<<NBG, 256>>>(x, Wd, bd, ts);
    // 3) normalize q,k; layernorm v
    k_norm<<<TOK, 256>>>(ln_g, ln_b);
    // 4) surprise = v - k @ M_prev^T (in place in g_v)
    k_nt<<<dim3(2, 4, NBG), 256>>>(Mprev, 0);
    // 5) M_next = clip(gamma*M_prev + surprise^T @ k / NPG)  -> d_out tail
    k_tn_mnext<<<dim3(2, 2, NBG), 256>>>(Mprev, Mnext);
    // 6) out_f = q @ M_next^T
    k_nt<<<dim3(2, 4, NBG), 256>>>(Mnext, 1);
    // 7) out = out_f @ Wo + bo
    k_out<<<dim3(16, 128), 256>>>(Wo, bo, out);
}

// round 5
// speedup vs baseline: 2.6950x; 2.6950x over previous
#include <cuda_runtime.h>
#include <math.h>
#include <stdint.h>

// Problem constants
#define TOK   16384      // B*N
#define DM    2048       // d_model
#define HD    256        // H
#define NBG   32         // B*G
#define NPG   512        // tokens per group
#define EPS   1e-5f

// GEMM tiling
#define BM 128
#define BN 128
#define BK 16
#define SST 136          // smem row stride (BM + 8) -> conflict-free frag loads

// ---------------------------------------------------------------------------
// Scratch (device globals; no allocations allowed)
// ---------------------------------------------------------------------------
__device__ float g_q[TOK * HD];
__device__ float g_k[TOK * HD];
__device__ float g_v[TOK * HD];     // v -> layernormed -> surprise (in place)
__device__ float g_of[TOK * HD];    // out_f
__device__ float g_gamma[NBG];
__device__ float g_gpart[NBG * 16];

// ---------------------------------------------------------------------------
// TF32 helpers
// ---------------------------------------------------------------------------
__device__ __forceinline__ uint32_t f2tf(float f) {
    uint32_t u;
    asm("cvt.rna.tf32.f32 %0, %1;" : "=r"(u) : "f"(f));
    return u;
}

__device__ __forceinline__ void mma8(float* d, const uint32_t* a, uint32_t b0, uint32_t b1) {
    asm volatile(
        "mma.sync.aligned.m16n8k8.row.col.f32.tf32.tf32.f32 "
        "{%0,%1,%2,%3},{%4,%5,%6,%7},{%8,%9},{%0,%1,%2,%3};"
        : "+f"(d[0]), "+f"(d[1]), "+f"(d[2]), "+f"(d[3])
        : "r"(a[0]), "r"(a[1]), "r"(a[2]), "r"(a[3]), "r"(b0), "r"(b1));
}

// Compute one BKx(BMxBN) tile from smem. All kernels share smem layout:
// As[k][m], Bs[k][n], k-major, stride SST.
__device__ __forceinline__ void mma_tile(const uint32_t* As, const uint32_t* Bs,
                                         float acc[4][4][4],
                                         int ltid, int grp, int wm, int wn)
{
    #pragma unroll
    for (int ks = 0; ks < 2; ks++) {
        const int kk = ks * 8;
        uint32_t a[4][4], b[4][2];
        #pragma unroll
        for (int mi = 0; mi < 4; mi++) {
            const int m = wm * 64 + mi * 16 + grp;
            a[mi][0] = As[(kk + ltid) * SST + m];
            a[mi][1] = As[(kk + ltid) * SST + m + 8];
            a[mi][2] = As[(kk + ltid + 4) * SST + m];
            a[mi][3] = As[(kk + ltid + 4) * SST + m + 8];
        }
        #pragma unroll
        for (int ni = 0; ni < 4; ni++) {
            const int n = wn * 32 + ni * 8 + grp;
            b[ni][0] = Bs[(kk + ltid) * SST + n];
            b[ni][1] = Bs[(kk + ltid + 4) * SST + n];
        }
        #pragma unroll
        for (int mi = 0; mi < 4; mi++)
            #pragma unroll
            for (int ni = 0; ni < 4; ni++)
                mma8(acc[mi][ni], a[mi], b[ni][0], b[ni][1]);
    }
}

// ---------------------------------------------------------------------------
// Generic NN GEMM: C[M,N] = A[M,K] @ B[K,N] + bias.  A,B row-major.
// asel: 0 -> use Aext, 1 -> g_of
// csel: 0 g_q, 1 g_k, 2 g_v, 3 Cext
// ---------------------------------------------------------------------------
__global__ __launch_bounds__(256, 2) void k_gemm_nn(
    const float* __restrict__ Aext, int asel, int lda,
    const float* __restrict__ B, int ldb,
    const float* __restrict__ bias,
    float* __restrict__ Cext, int csel, int ldc, int K)
{
    __shared__ uint32_t As[2][BK * SST];
    __shared__ uint32_t Bs[2][BK * SST];

    const float* A = asel ? g_of : Aext;
    float* C = (csel == 0) ? g_q : (csel == 1) ? g_k : (csel == 2) ? g_v : Cext;

    const int tid = threadIdx.x, lane = tid & 31, warp = tid >> 5;
    const int ltid = lane & 3, grp = lane >> 2;
    const int wm = warp & 1, wn = warp >> 1;
    const int m0 = blockIdx.y * BM, n0 = blockIdx.x * BN;

    const int am = tid >> 1, akb = (tid & 1) * 8;
    const int bk0 = tid >> 5, bn = lane * 4;

    const float* Ag = A + (size_t)(m0 + am) * lda + akb;
    const float* Bg = B + (size_t)bk0 * ldb + n0 + bn;

    float acc[4][4][4];
    #pragma unroll
    for (int i = 0; i < 4; i++)
        #pragma unroll
        for (int j = 0; j < 4; j++)
            #pragma unroll
            for (int l = 0; l < 4; l++) acc[i][j][l] = 0.f;

    float4 pa0, pa1, pb0, pb1;
    pa0 = *(const float4*)(Ag);
    pa1 = *(const float4*)(Ag + 4);
    pb0 = *(const float4*)(Bg);
    pb1 = *(const float4*)(Bg + (size_t)8 * ldb);

    auto stA = [&](uint32_t* dst) {
        dst[(akb + 0) * SST + am] = f2tf(pa0.x);
        dst[(akb + 1) * SST + am] = f2tf(pa0.y);
        dst[(akb + 2) * SST + am] = f2tf(pa0.z);
        dst[(akb + 3) * SST + am] = f2tf(pa0.w);
        dst[(akb + 4) * SST + am] = f2tf(pa1.x);
        dst[(akb + 5) * SST + am] = f2tf(pa1.y);
        dst[(akb + 6) * SST + am] = f2tf(pa1.z);
        dst[(akb + 7) * SST + am] = f2tf(pa1.w);
    };
    auto stB = [&](uint32_t* dst) {
        uint4 u0 = {f2tf(pb0.x), f2tf(pb0.y), f2tf(pb0.z), f2tf(pb0.w)};
        uint4 u1 = {f2tf(pb1.x), f2tf(pb1.y), f2tf(pb1.z), f2tf(pb1.w)};
        *(uint4*)&dst[bk0 * SST + bn] = u0;
        *(uint4*)&dst[(bk0 + 8) * SST + bn] = u1;
    };
    stA(As[0]); stB(Bs[0]);
    __syncthreads();

    const int KT = K / BK;
    int buf = 0;
    for (int kt = 0; kt < KT; kt++) {
        if (kt + 1 < KT) {
            const float* Ag2 = Ag + (size_t)(kt + 1) * BK;
            pa0 = *(const float4*)(Ag2);
            pa1 = *(const float4*)(Ag2 + 4);
            const float* Bg2 = Bg + (size_t)(kt + 1) * BK * ldb;
            pb0 = *(const float4*)(Bg2);
            pb1 = *(const float4*)(Bg2 + (size_t)8 * ldb);
        }
        mma_tile(As[buf], Bs[buf], acc, ltid, grp, wm, wn);
        if (kt + 1 < KT) {
            stA(As[buf ^ 1]); stB(Bs[buf ^ 1]);
            __syncthreads();
            buf ^= 1;
        }
    }

    #pragma unroll
    for (int mi = 0; mi < 4; mi++) {
        const int r0 = m0 + wm * 64 + mi * 16 + grp;
        #pragma unroll
        for (int ni = 0; ni < 4; ni++) {
            const int c = n0 + wn * 32 + ni * 8 + 2 * ltid;
            const float2 bia = *(const float2*)&bias[c];
            float2 o0 = {acc[mi][ni][0] + bia.x, acc[mi][ni][1] + bia.y};
            float2 o1 = {acc[mi][ni][2] + bia.x, acc[mi][ni][3] + bia.y};
            *(float2*)&C[(size_t)r0 * ldc + c] = o0;
            *(float2*)&C[(size_t)(r0 + 8) * ldc + c] = o1;
        }
    }
}

// ---------------------------------------------------------------------------
// Batched NT GEMM per group: C[n,m] = sum_h A[n,h] * Bm[m,h]
//   mode 0: A=g_k, C=g_v in place (surprise = v - k@M^T)
//   mode 1: A=g_q, C=g_of         (out_f = q@Mnext^T)
// grid: (2 n-tiles, 4 token-tiles, 32 groups)
// ---------------------------------------------------------------------------
__global__ __launch_bounds__(256, 2) void k_nt_tc(const float* __restrict__ Bbase, int mode)
{
    __shared__ uint32_t As[2][BK * SST];
    __shared__ uint32_t Bs[2][BK * SST];

    const int tid = threadIdx.x, lane = tid & 31, warp = tid >> 5;
    const int ltid = lane & 3, grp = lane >> 2;
    const int wm = warp & 1, wn = warp >> 1;
    const int bg = blockIdx.z;

    const float* A = (mode == 0 ? g_k : g_q) + (size_t)bg * NPG * HD;
    const float* Bm = Bbase + (size_t)bg * HD * HD;      // [N=256][K=256] row-major
    float* C = (mode == 0 ? g_v : g_of) + (size_t)bg * NPG * HD;

    const int n0 = blockIdx.x * BN, m0 = blockIdx.y * BM;

    const int am = tid >> 1, akb = (tid & 1) * 8;
    const float* Ag = A + (size_t)(m0 + am) * HD + akb;
    const float* Bg = Bm + (size_t)(n0 + am) * HD + akb;  // same staging pattern

    float acc[4][4][4];
    #pragma unroll
    for (int i = 0; i < 4; i++)
        #pragma unroll
        for (int j = 0; j < 4; j++)
            #pragma unroll
            for (int l = 0; l < 4; l++) acc[i][j][l] = 0.f;

    float4 pa0, pa1, pb0, pb1;
    pa0 = *(const float4*)(Ag);
    pa1 = *(const float4*)(Ag + 4);
    pb0 = *(const float4*)(Bg);
    pb1 = *(const float4*)(Bg + 4);

    auto stA = [&](uint32_t* dst) {
        dst[(akb + 0) * SST + am] = f2tf(pa0.x);
        dst[(akb + 1) * SST + am] = f2tf(pa0.y);
        dst[(akb + 2) * SST + am] = f2tf(pa0.z);
        dst[(akb + 3) * SST + am] = f2tf(pa0.w);
        dst[(akb + 4) * SST + am] = f2tf(pa1.x);
        dst[(akb + 5) * SST + am] = f2tf(pa1.y);
        dst[(akb + 6) * SST + am] = f2tf(pa1.z);
        dst[(akb + 7) * SST + am] = f2tf(pa1.w);
    };
    auto stB = [&](uint32_t* dst) {
        dst[(akb + 0) * SST + am] = f2tf(pb0.x);
        dst[(akb + 1) * SST + am] = f2tf(pb0.y);
        dst[(akb + 2) * SST + am] = f2tf(pb0.z);
        dst[(akb + 3) * SST + am] = f2tf(pb0.w);
        dst[(akb + 4) * SST + am] = f2tf(pb1.x);
        dst[(akb + 5) * SST + am] = f2tf(pb1.y);
        dst[(akb + 6) * SST + am] = f2tf(pb1.z);
        dst[(akb + 7) * SST + am] = f2tf(pb1.w);
    };
    stA(As[0]); stB(Bs[0]);
    __syncthreads();

    const int KT = HD / BK;  // 16
    int buf = 0;
    for (int kt = 0; kt < KT; kt++) {
        if (kt + 1 < KT) {
            const float* Ag2 = Ag + (size_t)(kt + 1) * BK;
            pa0 = *(const float4*)(Ag2);
            pa1 = *(const float4*)(Ag2 + 4);
            const float* Bg2 = Bg + (size_t)(kt + 1) * BK;
            pb0 = *(const float4*)(Bg2);
            pb1 = *(const float4*)(Bg2 + 4);
        }
        mma_tile(As[buf], Bs[buf], acc, ltid, grp, wm, wn);
        if (kt + 1 < KT) {
            stA(As[buf ^ 1]); stB(Bs[buf ^ 1]);
            __syncthreads();
            buf ^= 1;
        }
    }

    #pragma unroll
    for (int mi = 0; mi < 4; mi++) {
        const int r0 = m0 + wm * 64 + mi * 16 + grp;
        #pragma unroll
        for (int ni = 0; ni < 4; ni++) {
            const int c = n0 + wn * 32 + ni * 8 + 2 * ltid;
            const size_t i0 = (size_t)r0 * HD + c;
            const size_t i1 = (size_t)(r0 + 8) * HD + c;
            if (mode == 0) {
                float2 c0 = *(float2*)&C[i0];
                float2 c1 = *(float2*)&C[i1];
                float2 o0 = {c0.x - acc[mi][ni][0], c0.y - acc[mi][ni][1]};
                float2 o1 = {c1.x - acc[mi][ni][2], c1.y - acc[mi][ni][3]};
                *(float2*)&C[i0] = o0;
                *(float2*)&C[i1] = o1;
            } else {
                float2 o0 = {acc[mi][ni][0], acc[mi][ni][1]};
                float2 o1 = {acc[mi][ni][2], acc[mi][ni][3]};
                *(float2*)&C[i0] = o0;
                *(float2*)&C[i1] = o1;
            }
        }
    }
}

// ---------------------------------------------------------------------------
// Batched TN GEMM per group + M_next epilogue:
//   delta[m,h] = sum_n S[n,m] * K[n,h] / NPG
//   Mnext = clip(gamma*Mprev + delta, -10, 10)
// A = g_v (surprise) [512][256], B = g_k [512][256]; contraction = token dim.
// grid: (2 h-tiles, 2 m-tiles, 32 groups)
// ---------------------------------------------------------------------------
__global__ __launch_bounds__(256, 2) void k_tn_tc(
    const float* __restrict__ Mprev, float* __restrict__ Mnext)
{
    __shared__ uint32_t As[2][BK * SST];
    __shared__ uint32_t Bs[2][BK * SST];

    const int tid = threadIdx.x, lane = tid & 31, warp = tid >> 5;
    const int ltid = lane & 3, grp = lane >> 2;
    const int wm = warp & 1, wn = warp >> 1;
    const int bg = blockIdx.z;

    const float* A = g_v + (size_t)bg * NPG * HD;   // [K=512][M=256]
    const float* B = g_k + (size_t)bg * NPG * HD;   // [K=512][N=256]
    const int n0 = blockIdx.x * BN, m0 = blockIdx.y * BM;

    const int sk = tid >> 4, sc = (tid & 15) * 8;   // 16 k-rows x 128 cols
    const float* Ag = A + (size_t)sk * HD + m0 + sc;
    const float* Bg = B + (size_t)sk * HD + n0 + sc;

    float acc[4][4][4];
    #pragma unroll
    for (int i = 0; i < 4; i++)
        #pragma unroll
        for (int j = 0; j < 4; j++)
            #pragma unroll
            for (int l = 0; l < 4; l++) acc[i][j][l] = 0.f;

    float4 pa0, pa1, pb0, pb1;
    pa0 = *(const float4*)(Ag);
    pa1 = *(const float4*)(Ag + 4);
    pb0 = *(const float4*)(Bg);
    pb1 = *(const float4*)(Bg + 4);

    auto stA = [&](uint32_t* dst) {
        uint4 u0 = {f2tf(pa0.x), f2tf(pa0.y), f2tf(pa0.z), f2tf(pa0.w)};
        uint4 u1 = {f2tf(pa1.x), f2tf(pa1.y), f2tf(pa1.z), f2tf(pa1.w)};
        *(uint4*)&dst[sk * SST + sc] = u0;
        *(uint4*)&dst[sk * SST + sc + 4] = u1;
    };
    auto stB = [&](uint32_t* dst) {
        uint4 u0 = {f2tf(pb0.x), f2tf(pb0.y), f2tf(pb0.z), f2tf(pb0.w)};
        uint4 u1 = {f2tf(pb1.x), f2tf(pb1.y), f2tf(pb1.z), f2tf(pb1.w)};
        *(uint4*)&dst[sk * SST + sc] = u0;
        *(uint4*)&dst[sk * SST + sc + 4] = u1;
    };
    stA(As[0]); stB(Bs[0]);
    __syncthreads();

    const int KT = NPG / BK;  // 32
    int buf = 0;
    for (int kt = 0; kt < KT; kt++) {
        if (kt + 1 < KT) {
            const float* Ag2 = Ag + (size_t)(kt + 1) * BK * HD;
            pa0 = *(const float4*)(Ag2);
            pa1 = *(const float4*)(Ag2 + 4);
            const float* Bg2 = Bg + (size_t)(kt + 1) * BK * HD;
            pb0 = *(const float4*)(Bg2);
            pb1 = *(const float4*)(Bg2 + 4);
        }
        mma_tile(As[buf], Bs[buf], acc, ltid, grp, wm, wn);
        if (kt + 1 < KT) {
            stA(As[buf ^ 1]); stB(Bs[buf ^ 1]);
            __syncthreads();
            buf ^= 1;
        }
    }

    const float gam = g_gamma[bg];
    const float inv = 1.f / NPG;
    const size_t gbase = (size_t)bg * HD * HD;
    #pragma unroll
    for (int mi = 0; mi < 4; mi++) {
        const int m = m0 + wm * 64 + mi * 16 + grp;
        #pragma unroll
        for (int ni = 0; ni < 4; ni++) {
            const int h = n0 + wn * 32 + ni * 8 + 2 * ltid;
            const size_t i0 = gbase + (size_t)m * HD + h;
            const size_t i1 = gbase + (size_t)(m + 8) * HD + h;
            float2 p0 = *(const float2*)&Mprev[i0];
            float2 p1 = *(const float2*)&Mprev[i1];
            float2 o0, o1;
            o0.x = fminf(fmaxf(gam * p0.x + acc[mi][ni][0] * inv, -10.f), 10.f);
            o0.y = fminf(fmaxf(gam * p0.y + acc[mi][ni][1] * inv, -10.f), 10.f);
            o1.x = fminf(fmaxf(gam * p1.x + acc[mi][ni][2] * inv, -10.f), 10.f);
            o1.y = fminf(fmaxf(gam * p1.y + acc[mi][ni][3] * inv, -10.f), 10.f);
            *(float2*)&Mnext[i0] = o0;
            *(float2*)&Mnext[i1] = o1;
        }
    }
}

// ---------------------------------------------------------------------------
// Block-wide sum over 256 threads (8 warps)
// ---------------------------------------------------------------------------
__device__ __forceinline__ float blockSum256(float v) {
    __shared__ float red[8];
    #pragma unroll
    for (int o = 16; o > 0; o >>= 1) v += __shfl_xor_sync(0xffffffffu, v, o);
    if ((threadIdx.x & 31) == 0) red[threadIdx.x >> 5] = v;
    __syncthreads();
    float s = red[0] + red[1] + red[2] + red[3] + red[4] + red[5] + red[6] + red[7];
    __syncthreads();
    return s;
}

// ---------------------------------------------------------------------------
// gamma: stage 1 — 512 blocks, each sums 32 rows of x . Wd
// ---------------------------------------------------------------------------
__global__ __launch_bounds__(256) void k_gamma1(
    const float* __restrict__ x, const float* __restrict__ Wd)
{
    const int bg = blockIdx.x >> 4, ch = blockIdx.x & 15;
    const float* xr = x + ((size_t)bg * NPG + (size_t)ch * 32) * DM;
    float acc = 0.f;
    for (int n = 0; n < 32; n++) {
        const float* row = xr + (size_t)n * DM;
        for (int c = threadIdx.x; c < DM; c += 256)
            acc = fmaf(row[c], Wd[c], acc);
    }
    float s = blockSum256(acc);
    if (threadIdx.x == 0) g_gpart[blockIdx.x] = s;
}

// gamma: stage 2 — finalize 32 gates
__global__ void k_gamma2(const float* __restrict__ bd, const float* __restrict__ ts)
{
    const int bg = threadIdx.x;  // 32 threads
    float s = 0.f;
    #pragma unroll
    for (int i = 0; i < 16; i++) s += g_gpart[bg * 16 + i];
    float z = s * (1.f / NPG) + bd[0] + ts[bg & 7];
    g_gamma[bg] = 1.f / (1.f + expf(-z));
}

// ---------------------------------------------------------------------------
// Row normalization: q,k L2-normalize; v layernorm. One block per token.
// ---------------------------------------------------------------------------
__global__ __launch_bounds__(256) void k_norm(
    const float* __restrict__ ln_g, const float* __restrict__ ln_b)
{
    const int r = blockIdx.x, t = threadIdx.x;
    const size_t idx = (size_t)r * HD + t;

    float qv = g_q[idx];
    float s = blockSum256(qv * qv);
    g_q[idx] = qv / fmaxf(sqrtf(s), EPS);

    float kv = g_k[idx];
    s = blockSum256(kv * kv);
    g_k[idx] = kv / fmaxf(sqrtf(s), EPS);

    float vv = g_v[idx];
    float mu = blockSum256(vv) * (1.f / HD);
    float d = vv - mu;
    float var = blockSum256(d * d) * (1.f / HD);
    g_v[idx] = d * rsqrtf(var + EPS) * ln_g[t] + ln_b[t];
}

// ---------------------------------------------------------------------------
// Launch
// ---------------------------------------------------------------------------
extern "C" void kernel_launch(void* const* d_in, const int* in_sizes, int n_in,
                              void* d_out, int out_size)
{
    const float* x     = (const float*)d_in[0];
    const float* Mprev = (const float*)d_in[1];
    const float* Wq    = (const float*)d_in[2];
    const float* bq    = (const float*)d_in[3];
    const float* Wk    = (const float*)d_in[4];
    const float* bk    = (const float*)d_in[5];
    const float* Wv    = (const float*)d_in[6];
    const float* bv    = (const float*)d_in[7];
    const float* ln_g  = (const float*)d_in[8];
    const float* ln_b  = (const float*)d_in[9];
    const float* Wo    = (const float*)d_in[10];
    const float* bo    = (const float*)d_in[11];
    const float* Wd    = (const float*)d_in[12];
    const float* bd    = (const float*)d_in[13];
    const float* ts    = (const float*)d_in[14];

    float* out   = (float*)d_out;
    float* Mnext = out + (size_t)TOK * DM;

    // q,k,v projections (TF32 tensor cores)
    k_gemm_nn<<<dim3(2, 128), 256>>>(x, 0, DM, Wq, HD, bq, nullptr, 0, HD, DM);
    k_gemm_nn<<<dim3(2, 128), 256>>>(x, 0, DM, Wk, HD, bk, nullptr, 1, HD, DM);
    k_gemm_nn<<<dim3(2, 128), 256>>>(x, 0, DM, Wv, HD, bv, nullptr, 2, HD, DM);
    // gate gamma
    k_gamma1<<<512, 256>>>(x, Wd);
    k_gamma2<<<1, 32>>>(bd, ts);
    // normalize q,k; layernorm v
    k_norm<<<TOK, 256>>>(ln_g, ln_b);
    // surprise = v - k @ Mprev^T (in place)
    k_nt_tc<<<dim3(2, 4, NBG), 256>>>(Mprev, 0);
    // Mnext = clip(gamma*Mprev + surprise^T @ k / NPG)
    k_tn_tc<<<dim3(2, 2, NBG), 256>>>(Mprev, Mnext);
    // out_f = q @ Mnext^T
    k_nt_tc<<<dim3(2, 4, NBG), 256>>>(Mnext, 1);
    // out = out_f @ Wo + bo
    k_gemm_nn<<<dim3(16, 128), 256>>>(g_of, 1, HD, Wo, DM, bo, out, 3, DM, HD);
}

// round 6
// speedup vs baseline: 3.0829x; 1.1439x over previous
#include <cuda_runtime.h>
#include <math.h>
#include <stdint.h>

// Problem constants
#define TOK   16384      // B*N
#define DM    2048       // d_model
#define HD    256        // H
#define NBG   32         // B*G
#define NPG   512        // tokens per group
#define EPS   1e-5f

// smem layout strides (floats)
#define RKS 20           // row-major tile [row][k=16], padded -> bank-conflict-free frags
#define KMS 136          // k-major tile [k=16][col=128], padded

// ---------------------------------------------------------------------------
// Scratch (device globals; no allocations allowed)
// ---------------------------------------------------------------------------
__device__ float g_q[TOK * HD];          // q (raw -> normalized, tf32-rounded)
__device__ float g_k[TOK * HD];          // k (raw -> normalized, tf32-rounded)
__device__ float g_v[TOK * HD];          // v -> layernorm -> surprise (rounded)
__device__ float g_of[TOK * HD];         // out_f (tf32-rounded)
__device__ float g_wq[DM * HD];          // tf32-rounded weights
__device__ float g_wk[DM * HD];
__device__ float g_wv[DM * HD];
__device__ float g_wo[HD * DM];
__device__ float g_mp[NBG * HD * HD];    // tf32-rounded M_prev
__device__ float g_mn[NBG * HD * HD];    // tf32-rounded M_next (GEMM operand copy)
__device__ float g_gamma[NBG];
__device__ float g_gpart[512];

// ---------------------------------------------------------------------------
// Helpers
// ---------------------------------------------------------------------------
__device__ __forceinline__ uint32_t f2tf(float f) {
    uint32_t u;
    asm("cvt.rna.tf32.f32 %0, %1;" : "=r"(u) : "f"(f));
    return u;
}
__device__ __forceinline__ float rtf(float f) { return __uint_as_float(f2tf(f)); }

__device__ __forceinline__ uint32_t s2u(const void* p) {
    return (uint32_t)__cvta_generic_to_shared(p);
}
__device__ __forceinline__ void cpa16(uint32_t dst, const float* src) {
    asm volatile("cp.async.cg.shared.global [%0], [%1], 16;" :: "r"(dst), "l"(src));
}
#define CP_COMMIT() asm volatile("cp.async.commit_group;")
#define CP_WAIT1()  asm volatile("cp.async.wait_group 1;")

__device__ __forceinline__ void mma8(float* d, const uint32_t* a, uint32_t b0, uint32_t b1) {
    asm volatile(
        "mma.sync.aligned.m16n8k8.row.col.f32.tf32.tf32.f32 "
        "{%0,%1,%2,%3},{%4,%5,%6,%7},{%8,%9},{%0,%1,%2,%3};"
        : "+f"(d[0]), "+f"(d[1]), "+f"(d[2]), "+f"(d[3])
        : "r"(a[0]), "r"(a[1]), "r"(a[2]), "r"(a[3]), "r"(b0), "r"(b1));
}

__device__ __forceinline__ void mma_step(float acc[4][4][4],
                                         const uint32_t a[4][4], const uint32_t b[4][2]) {
    #pragma unroll
    for (int mi = 0; mi < 4; mi++)
        #pragma unroll
        for (int ni = 0; ni < 4; ni++)
            mma8(acc[mi][ni], a[mi], b[ni][0], b[ni][1]);
}

// Fragment loaders. Conventions match the verified round-5 kernel:
//   a[mi] = { (k,m), (k,m+8), (k+4,m), (k+4,m+8) }, b[ni] = { (k,n), (k+4,n) }
__device__ __forceinline__ void ldA_rowK(uint32_t a[4][4], const float* As,
                                         int kk, int ltid, int grp, int wm) {
    #pragma unroll
    for (int mi = 0; mi < 4; mi++) {
        const float* p = As + (wm * 64 + mi * 16 + grp) * RKS + kk + ltid;
        a[mi][0] = __float_as_uint(p[0]);
        a[mi][1] = __float_as_uint(p[8 * RKS]);
        a[mi][2] = __float_as_uint(p[4]);
        a[mi][3] = __float_as_uint(p[8 * RKS + 4]);
    }
}
__device__ __forceinline__ void ldA_kMaj(uint32_t a[4][4], const float* As,
                                         int kk, int ltid, int grp, int wm) {
    #pragma unroll
    for (int mi = 0; mi < 4; mi++) {
        const float* p = As + (kk + ltid) * KMS + wm * 64 + mi * 16 + grp;
        a[mi][0] = __float_as_uint(p[0]);
        a[mi][1] = __float_as_uint(p[8]);
        a[mi][2] = __float_as_uint(p[4 * KMS]);
        a[mi][3] = __float_as_uint(p[4 * KMS + 8]);
    }
}
__device__ __forceinline__ void ldB_rowK(uint32_t b[4][2], const float* Bs,
                                         int kk, int ltid, int grp, int wn) {
    #pragma unroll
    for (int ni = 0; ni < 4; ni++) {
        const float* p = Bs + (wn * 32 + ni * 8 + grp) * RKS + kk + ltid;
        b[ni][0] = __float_as_uint(p[0]);
        b[ni][1] = __float_as_uint(p[4]);
    }
}
__device__ __forceinline__ void ldB_kMaj(uint32_t b[4][2], const float* Bs,
                                         int kk, int ltid, int grp, int wn) {
    #pragma unroll
    for (int ni = 0; ni < 4; ni++) {
        const float* p = Bs + (kk + ltid) * KMS + wn * 32 + ni * 8 + grp;
        b[ni][0] = __float_as_uint(p[0]);
        b[ni][1] = __float_as_uint(p[4 * KMS]);
    }
}

// Stage copies: 512 x 16B chunks, 2 per thread.
// rowK: 128 rows x 16 floats from row-major global (ld = row stride)
__device__ __forceinline__ void cp_rowK(float* dst, const float* src, int ld, int tid) {
    #pragma unroll
    for (int i = 0; i < 2; i++) {
        const int c = tid * 2 + i;
        const int r = c >> 2, kc = (c & 3) * 4;
        cpa16(s2u(dst + r * RKS + kc), src + (size_t)r * ld + kc);
    }
}
// kMaj: 16 rows x 128 floats
__device__ __forceinline__ void cp_kMaj(float* dst, const float* src, int ld, int tid) {
    #pragma unroll
    for (int i = 0; i < 2; i++) {
        const int c = tid * 2 + i;
        const int r = c >> 5, col = (c & 31) * 4;
        cpa16(s2u(dst + r * KMS + col), src + (size_t)r * ld + col);
    }
}

#define ZERO_ACC(acc)                         \
    _Pragma("unroll")                         \
    for (int i = 0; i < 4; i++)               \
        _Pragma("unroll")                     \
        for (int j = 0; j < 4; j++)           \
            _Pragma("unroll")                 \
            for (int l = 0; l < 4; l++) acc[i][j][l] = 0.f;

// ---------------------------------------------------------------------------
// Kernel: fused QKV GEMM.  C = x @ W + b for W in {wq,wk,wv} (pre-rounded).
// x consumed raw (HMMA truncation). grid (6, 128); bx fastest -> x tiles L2-hot.
// ---------------------------------------------------------------------------
__global__ __launch_bounds__(256, 2) void k_qkv(
    const float* __restrict__ x,
    const float* __restrict__ bq, const float* __restrict__ bk,
    const float* __restrict__ bv)
{
    extern __shared__ float sm[];
    float* As = sm;                    // 3 stages x 128*RKS
    float* Bs = sm + 3 * 128 * RKS;    // 3 stages x 16*KMS

    const int tid = threadIdx.x, lane = tid & 31, warp = tid >> 5;
    const int ltid = lane & 3, grp = lane >> 2;
    const int wm = warp & 1, wn = warp >> 1;

    const int which = blockIdx.x >> 1;
    const int n0 = (blockIdx.x & 1) * 128;
    const int m0 = blockIdx.y * 128;

    const float* W    = (which == 0) ? g_wq : (which == 1) ? g_wk : g_wv;
    const float* bias = (which == 0) ? bq : (which == 1) ? bk : bv;
    float* C          = (which == 0) ? g_q : (which == 1) ? g_k : g_v;

    const float* Ab = x + (size_t)m0 * DM;
    const float* Bb = W + n0;

    cp_rowK(As, Ab, DM, tid);
    cp_kMaj(Bs, Bb, HD, tid);
    CP_COMMIT();
    cp_rowK(As + 128 * RKS, Ab + 16, DM, tid);
    cp_kMaj(Bs + 16 * KMS, Bb + (size_t)16 * HD, HD, tid);
    CP_COMMIT();

    float acc[4][4][4];
    ZERO_ACC(acc);

    const int KT = DM / 16;   // 128
    int st = 0;
    for (int kt = 0; kt < KT; kt++) {
        CP_WAIT1();
        __syncthreads();
        const int nx = kt + 2;
        if (nx < KT) {
            const int sn = (st + 2 >= 3) ? st - 1 : st + 2;
            cp_rowK(As + sn * 128 * RKS, Ab + nx * 16, DM, tid);
            cp_kMaj(Bs + sn * 16 * KMS, Bb + (size_t)nx * 16 * HD, HD, tid);
        }
        CP_COMMIT();
        const float* Ast = As + st * 128 * RKS;
        const float* Bst = Bs + st * 16 * KMS;
        uint32_t a[4][4], b[4][2];
        #pragma unroll
        for (int ks = 0; ks < 2; ks++) {
            ldA_rowK(a, Ast, ks * 8, ltid, grp, wm);
            ldB_kMaj(b, Bst, ks * 8, ltid, grp, wn);
            mma_step(acc, a, b);
        }
        st++; if (st == 3) st = 0;
    }

    #pragma unroll
    for (int mi = 0; mi < 4; mi++) {
        const int r0 = m0 + wm * 64 + mi * 16 + grp;
        #pragma unroll
        for (int ni = 0; ni < 4; ni++) {
            const int c = n0 + wn * 32 + ni * 8 + 2 * ltid;
            const float2 bia = *(const float2*)&bias[c];
            float2 o0 = {acc[mi][ni][0] + bia.x, acc[mi][ni][1] + bia.y};
            float2 o1 = {acc[mi][ni][2] + bia.x, acc[mi][ni][3] + bia.y};
            *(float2*)&C[(size_t)r0 * HD + c] = o0;
            *(float2*)&C[(size_t)(r0 + 8) * HD + c] = o1;
        }
    }
}

// ---------------------------------------------------------------------------
// Kernel: final GEMM.  out = g_of @ g_wo + bo.  grid (16, 128).
// ---------------------------------------------------------------------------
__global__ __launch_bounds__(256, 2) void k_out(
    const float* __restrict__ bo, float* __restrict__ out)
{
    extern __shared__ float sm[];
    float* As = sm;
    float* Bs = sm + 3 * 128 * RKS;

    const int tid = threadIdx.x, lane = tid & 31, warp = tid >> 5;
    const int ltid = lane & 3, grp = lane >> 2;
    const int wm = warp & 1, wn = warp >> 1;
    const int n0 = blockIdx.x * 128;
    const int m0 = blockIdx.y * 128;

    const float* Ab = g_of + (size_t)m0 * HD;
    const float* Bb = g_wo + n0;

    cp_rowK(As, Ab, HD, tid);
    cp_kMaj(Bs, Bb, DM, tid);
    CP_COMMIT();
    cp_rowK(As + 128 * RKS, Ab + 16, HD, tid);
    cp_kMaj(Bs + 16 * KMS, Bb + (size_t)16 * DM, DM, tid);
    CP_COMMIT();

    float acc[4][4][4];
    ZERO_ACC(acc);

    const int KT = HD / 16;   // 16
    int st = 0;
    for (int kt = 0; kt < KT; kt++) {
        CP_WAIT1();
        __syncthreads();
        const int nx = kt + 2;
        if (nx < KT) {
            const int sn = (st + 2 >= 3) ? st - 1 : st + 2;
            cp_rowK(As + sn * 128 * RKS, Ab + nx * 16, HD, tid);
            cp_kMaj(Bs + sn * 16 * KMS, Bb + (size_t)nx * 16 * DM, DM, tid);
        }
        CP_COMMIT();
        const float* Ast = As + st * 128 * RKS;
        const float* Bst = Bs + st * 16 * KMS;
        uint32_t a[4][4], b[4][2];
        #pragma unroll
        for (int ks = 0; ks < 2; ks++) {
            ldA_rowK(a, Ast, ks * 8, ltid, grp, wm);
            ldB_kMaj(b, Bst, ks * 8, ltid, grp, wn);
            mma_step(acc, a, b);
        }
        st++; if (st == 3) st = 0;
    }

    #pragma unroll
    for (int mi = 0; mi < 4; mi++) {
        const int r0 = m0 + wm * 64 + mi * 16 + grp;
        #pragma unroll
        for (int ni = 0; ni < 4; ni++) {
            const int c = n0 + wn * 32 + ni * 8 + 2 * ltid;
            const float2 bia = *(const float2*)&bo[c];
            float2 o0 = {acc[mi][ni][0] + bia.x, acc[mi][ni][1] + bia.y};
            float2 o1 = {acc[mi][ni][2] + bia.x, acc[mi][ni][3] + bia.y};
            *(float2*)&out[(size_t)r0 * DM + c] = o0;
            *(float2*)&out[(size_t)(r0 + 8) * DM + c] = o1;
        }
    }
}

// ---------------------------------------------------------------------------
// Kernel: batched NT GEMM per group.  C[n,m] = sum_h A[n,h]*Bm[m,h]
//   mode 0: A=g_k, B=g_mp, C=g_v in place (surprise, tf32-rounded store)
//   mode 1: A=g_q, B=g_mn, C=g_of (tf32-rounded store)
// grid (2, 4, 32)
// ---------------------------------------------------------------------------
__global__ __launch_bounds__(256, 2) void k_nt(int mode)
{
    extern __shared__ float sm[];
    float* As = sm;
    float* Bs = sm + 3 * 128 * RKS;

    const int tid = threadIdx.x, lane = tid & 31, warp = tid >> 5;
    const int ltid = lane & 3, grp = lane >> 2;
    const int wm = warp & 1, wn = warp >> 1;
    const int bg = blockIdx.z;
    const int n0 = blockIdx.x * 128;
    const int m0 = blockIdx.y * 128;

    const float* Ab = (mode == 0 ? g_k : g_q) + (size_t)bg * NPG * HD + (size_t)m0 * HD;
    const float* Bb = (mode == 0 ? g_mp : g_mn) + (size_t)bg * HD * HD + (size_t)n0 * HD;
    float* C = (mode == 0 ? g_v : g_of) + (size_t)bg * NPG * HD;

    cp_rowK(As, Ab, HD, tid);
    cp_rowK(Bs, Bb, HD, tid);
    CP_COMMIT();
    cp_rowK(As + 128 * RKS, Ab + 16, HD, tid);
    cp_rowK(Bs + 128 * RKS, Bb + 16, HD, tid);
    CP_COMMIT();

    float acc[4][4][4];
    ZERO_ACC(acc);

    const int KT = HD / 16;   // 16
    int st = 0;
    for (int kt = 0; kt < KT; kt++) {
        CP_WAIT1();
        __syncthreads();
        const int nx = kt + 2;
        if (nx < KT) {
            const int sn = (st + 2 >= 3) ? st - 1 : st + 2;
            cp_rowK(As + sn * 128 * RKS, Ab + nx * 16, HD, tid);
            cp_rowK(Bs + sn * 128 * RKS, Bb + nx * 16, HD, tid);
        }
        CP_COMMIT();
        const float* Ast = As + st * 128 * RKS;
        const float* Bst = Bs + st * 128 * RKS;
        uint32_t a[4][4], b[4][2];
        #pragma unroll
        for (int ks = 0; ks < 2; ks++) {
            ldA_rowK(a, Ast, ks * 8, ltid, grp, wm);
            ldB_rowK(b, Bst, ks * 8, ltid, grp, wn);
            mma_step(acc, a, b);
        }
        st++; if (st == 3) st = 0;
    }

    #pragma unroll
    for (int mi = 0; mi < 4; mi++) {
        const int r0 = m0 + wm * 64 + mi * 16 + grp;
        #pragma unroll
        for (int ni = 0; ni < 4; ni++) {
            const int c = n0 + wn * 32 + ni * 8 + 2 * ltid;
            const size_t i0 = (size_t)r0 * HD + c;
            const size_t i1 = (size_t)(r0 + 8) * HD + c;
            if (mode == 0) {
                float2 c0 = *(float2*)&C[i0];
                float2 c1 = *(float2*)&C[i1];
                float2 o0 = {rtf(c0.x - acc[mi][ni][0]), rtf(c0.y - acc[mi][ni][1])};
                float2 o1 = {rtf(c1.x - acc[mi][ni][2]), rtf(c1.y - acc[mi][ni][3])};
                *(float2*)&C[i0] = o0;
                *(float2*)&C[i1] = o1;
            } else {
                float2 o0 = {rtf(acc[mi][ni][0]), rtf(acc[mi][ni][1])};
                float2 o1 = {rtf(acc[mi][ni][2]), rtf(acc[mi][ni][3])};
                *(float2*)&C[i0] = o0;
                *(float2*)&C[i1] = o1;
            }
        }
    }
}

// ---------------------------------------------------------------------------
// Kernel: batched TN GEMM + M_next epilogue.
//   delta[m,h] = sum_n surprise[n,m]*k[n,h] / NPG
//   Mnext = clip(gamma*Mprev + delta) -> fp32 to d_out, tf32-rounded to g_mn
// grid (2, 2, 32)
// ---------------------------------------------------------------------------
__global__ __launch_bounds__(256, 2) void k_tn(
    const float* __restrict__ Mprev, float* __restrict__ Mnext)
{
    extern __shared__ float sm[];
    float* As = sm;
    float* Bs = sm + 3 * 16 * KMS;

    const int tid = threadIdx.x, lane = tid & 31, warp = tid >> 5;
    const int ltid = lane & 3, grp = lane >> 2;
    const int wm = warp & 1, wn = warp >> 1;
    const int bg = blockIdx.z;
    const int n0 = blockIdx.x * 128;   // h
    const int m0 = blockIdx.y * 128;   // m (surprise feature)

    const float* Ab = g_v + (size_t)bg * NPG * HD + m0;   // [512][256], k-major
    const float* Bb = g_k + (size_t)bg * NPG * HD + n0;

    cp_kMaj(As, Ab, HD, tid);
    cp_kMaj(Bs, Bb, HD, tid);
    CP_COMMIT();
    cp_kMaj(As + 16 * KMS, Ab + (size_t)16 * HD, HD, tid);
    cp_kMaj(Bs + 16 * KMS, Bb + (size_t)16 * HD, HD, tid);
    CP_COMMIT();

    float acc[4][4][4];
    ZERO_ACC(acc);

    const int KT = NPG / 16;   // 32
    int st = 0;
    for (int kt = 0; kt < KT; kt++) {
        CP_WAIT1();
        __syncthreads();
        const int nx = kt + 2;
        if (nx < KT) {
            const int sn = (st + 2 >= 3) ? st - 1 : st + 2;
            cp_kMaj(As + sn * 16 * KMS, Ab + (size_t)nx * 16 * HD, HD, tid);
            cp_kMaj(Bs + sn * 16 * KMS, Bb + (size_t)nx * 16 * HD, HD, tid);
        }
        CP_COMMIT();
        const float* Ast = As + st * 16 * KMS;
        const float* Bst = Bs + st * 16 * KMS;
        uint32_t a[4][4], b[4][2];
        #pragma unroll
        for (int ks = 0; ks < 2; ks++) {
            ldA_kMaj(a, Ast, ks * 8, ltid, grp, wm);
            ldB_kMaj(b, Bst, ks * 8, ltid, grp, wn);
            mma_step(acc, a, b);
        }
        st++; if (st == 3) st = 0;
    }

    const float gam = g_gamma[bg];
    const float inv = 1.f / NPG;
    const size_t gbase = (size_t)bg * HD * HD;
    #pragma unroll
    for (int mi = 0; mi < 4; mi++) {
        const int m = m0 + wm * 64 + mi * 16 + grp;
        #pragma unroll
        for (int ni = 0; ni < 4; ni++) {
            const int h = n0 + wn * 32 + ni * 8 + 2 * ltid;
            const size_t i0 = gbase + (size_t)m * HD + h;
            const size_t i1 = gbase + (size_t)(m + 8) * HD + h;
            float2 p0 = *(const float2*)&Mprev[i0];
            float2 p1 = *(const float2*)&Mprev[i1];
            float2 o0, o1;
            o0.x = fminf(fmaxf(gam * p0.x + acc[mi][ni][0] * inv, -10.f), 10.f);
            o0.y = fminf(fmaxf(gam * p0.y + acc[mi][ni][1] * inv, -10.f), 10.f);
            o1.x = fminf(fmaxf(gam * p1.x + acc[mi][ni][2] * inv, -10.f), 10.f);
            o1.y = fminf(fmaxf(gam * p1.y + acc[mi][ni][3] * inv, -10.f), 10.f);
            *(float2*)&Mnext[i0] = o0;
            *(float2*)&Mnext[i1] = o1;
            float2 r0 = {rtf(o0.x), rtf(o0.y)};
            float2 r1 = {rtf(o1.x), rtf(o1.y)};
            *(float2*)&g_mn[i0] = r0;
            *(float2*)&g_mn[i1] = r1;
        }
    }
}

// ---------------------------------------------------------------------------
// Pre-round weights + M_prev to tf32. 1048576 float4 elements total.
// ---------------------------------------------------------------------------
__global__ __launch_bounds__(256) void k_round(
    const float* __restrict__ Wq, const float* __restrict__ Wk,
    const float* __restrict__ Wv, const float* __restrict__ Wo,
    const float* __restrict__ Mp)
{
    const int i = blockIdx.x * 256 + threadIdx.x;   // float4 index
    const float4* src; float4* dst; int off;
    if      (i < 131072) { src = (const float4*)Wq; dst = (float4*)g_wq; off = i; }
    else if (i < 262144) { src = (const float4*)Wk; dst = (float4*)g_wk; off = i - 131072; }
    else if (i < 393216) { src = (const float4*)Wv; dst = (float4*)g_wv; off = i - 262144; }
    else if (i < 524288) { src = (const float4*)Wo; dst = (float4*)g_wo; off = i - 393216; }
    else                 { src = (const float4*)Mp; dst = (float4*)g_mp; off = i - 524288; }
    float4 v = src[off];
    v.x = rtf(v.x); v.y = rtf(v.y); v.z = rtf(v.z); v.w = rtf(v.w);
    dst[off] = v;
}

// ---------------------------------------------------------------------------
// gamma stage 1: 512 blocks, each sums 32 rows of x . Wd (float4 loads)
// ---------------------------------------------------------------------------
__global__ __launch_bounds__(256) void k_gamma1(
    const float* __restrict__ x, const float* __restrict__ Wd)
{
    const int bg = blockIdx.x >> 4, ch = blockIdx.x & 15;
    const float4* xr = (const float4*)(x + ((size_t)bg * NPG + (size_t)ch * 32) * DM);
    const float4* wd = (const float4*)Wd;
    float acc = 0.f;
    for (int n = 0; n < 32; n++) {
        const float4* row = xr + (size_t)n * (DM / 4);
        #pragma unroll
        for (int c = threadIdx.x; c < DM / 4; c += 256) {
            float4 a = row[c], w = wd[c];
            acc += a.x * w.x + a.y * w.y + a.z * w.z + a.w * w.w;
        }
    }
    __shared__ float red[8];
    #pragma unroll
    for (int o = 16; o > 0; o >>= 1) acc += __shfl_xor_sync(0xffffffffu, acc, o);
    if ((threadIdx.x & 31) == 0) red[threadIdx.x >> 5] = acc;
    __syncthreads();
    if (threadIdx.x == 0) {
        float s = red[0] + red[1] + red[2] + red[3] + red[4] + red[5] + red[6] + red[7];
        g_gpart[blockIdx.x] = s;
    }
}

__global__ void k_gamma2(const float* __restrict__ bd, const float* __restrict__ ts)
{
    const int bg = threadIdx.x;   // 32 threads
    float s = 0.f;
    #pragma unroll
    for (int i = 0; i < 16; i++) s += g_gpart[bg * 16 + i];
    float z = s * (1.f / NPG) + bd[0] + ts[bg & 7];
    g_gamma[bg] = 1.f / (1.f + expf(-z));
}

// ---------------------------------------------------------------------------
// Row normalization, warp-per-row (8 rows/block, no barriers).
// q,k: L2-normalize + tf32-round. v: layernorm (fp32, rounded later as surprise).
// ---------------------------------------------------------------------------
__global__ __launch_bounds__(256) void k_norm(
    const float* __restrict__ ln_g, const float* __restrict__ ln_b)
{
    const int lane = threadIdx.x & 31, warp = threadIdx.x >> 5;
    const int row = blockIdx.x * 8 + warp;
    const size_t base = (size_t)row * HD + lane * 8;

    // q
    float4 q0 = *(const float4*)&g_q[base];
    float4 q1 = *(const float4*)&g_q[base + 4];
    float s = q0.x*q0.x + q0.y*q0.y + q0.z*q0.z + q0.w*q0.w
            + q1.x*q1.x + q1.y*q1.y + q1.z*q1.z + q1.w*q1.w;
    #pragma unroll
    for (int o = 16; o > 0; o >>= 1) s += __shfl_xor_sync(0xffffffffu, s, o);
    float r = 1.f / fmaxf(sqrtf(s), EPS);
    q0.x = rtf(q0.x*r); q0.y = rtf(q0.y*r); q0.z = rtf(q0.z*r); q0.w = rtf(q0.w*r);
    q1.x = rtf(q1.x*r); q1.y = rtf(q1.y*r); q1.z = rtf(q1.z*r); q1.w = rtf(q1.w*r);
    *(float4*)&g_q[base] = q0;
    *(float4*)&g_q[base + 4] = q1;

    // k
    float4 k0 = *(const float4*)&g_k[base];
    float4 k1 = *(const float4*)&g_k[base + 4];
    s = k0.x*k0.x + k0.y*k0.y + k0.z*k0.z + k0.w*k0.w
      + k1.x*k1.x + k1.y*k1.y + k1.z*k1.z + k1.w*k1.w;
    #pragma unroll
    for (int o = 16; o > 0; o >>= 1) s += __shfl_xor_sync(0xffffffffu, s, o);
    r = 1.f / fmaxf(sqrtf(s), EPS);
    k0.x = rtf(k0.x*r); k0.y = rtf(k0.y*r); k0.z = rtf(k0.z*r); k0.w = rtf(k0.w*r);
    k1.x = rtf(k1.x*r); k1.y = rtf(k1.y*r); k1.z = rtf(k1.z*r); k1.w = rtf(k1.w*r);
    *(float4*)&g_k[base] = k0;
    *(float4*)&g_k[base + 4] = k1;

    // v: layernorm (stay fp32)
    float4 v0 = *(const float4*)&g_v[base];
    float4 v1 = *(const float4*)&g_v[base + 4];
    float s1 = v0.x + v0.y + v0.z + v0.w + v1.x + v1.y + v1.z + v1.w;
    float s2 = v0.x*v0.x + v0.y*v0.y + v0.z*v0.z + v0.w*v0.w
             + v1.x*v1.x + v1.y*v1.y + v1.z*v1.z + v1.w*v1.w;
    #pragma unroll
    for (int o = 16; o > 0; o >>= 1) {
        s1 += __shfl_xor_sync(0xffffffffu, s1, o);
        s2 += __shfl_xor_sync(0xffffffffu, s2, o);
    }
    const float mu = s1 * (1.f / HD);
    const float var = s2 * (1.f / HD) - mu * mu;
    const float rstd = rsqrtf(var + EPS);
    float4 gg0 = *(const float4*)&ln_g[lane * 8];
    float4 gg1 = *(const float4*)&ln_g[lane * 8 + 4];
    float4 bb0 = *(const float4*)&ln_b[lane * 8];
    float4 bb1 = *(const float4*)&ln_b[lane * 8 + 4];
    v0.x = (v0.x - mu) * rstd * gg0.x + bb0.x;
    v0.y = (v0.y - mu) * rstd * gg0.y + bb0.y;
    v0.z = (v0.z - mu) * rstd * gg0.z + bb0.z;
    v0.w = (v0.w - mu) * rstd * gg0.w + bb0.w;
    v1.x = (v1.x - mu) * rstd * gg1.x + bb1.x;
    v1.y = (v1.y - mu) * rstd * gg1.y + bb1.y;
    v1.z = (v1.z - mu) * rstd * gg1.z + bb1.z;
    v1.w = (v1.w - mu) * rstd * gg1.w + bb1.w;
    *(float4*)&g_v[base] = v0;
    *(float4*)&g_v[base + 4] = v1;
}

// ---------------------------------------------------------------------------
// Launch
// ---------------------------------------------------------------------------
extern "C" void kernel_launch(void* const* d_in, const int* in_sizes, int n_in,
                              void* d_out, int out_size)
{
    const float* x     = (const float*)d_in[0];
    const float* Mprev = (const float*)d_in[1];
    const float* Wq    = (const float*)d_in[2];
    const float* bq    = (const float*)d_in[3];
    const float* Wk    = (const float*)d_in[4];
    const float* bk    = (const float*)d_in[5];
    const float* Wv    = (const float*)d_in[6];
    const float* bv    = (const float*)d_in[7];
    const float* ln_g  = (const float*)d_in[8];
    const float* ln_b  = (const float*)d_in[9];
    const float* Wo    = (const float*)d_in[10];
    const float* bo    = (const float*)d_in[11];
    const float* Wd    = (const float*)d_in[12];
    const float* bd    = (const float*)d_in[13];
    const float* ts    = (const float*)d_in[14];

    float* out   = (float*)d_out;
    float* Mnext = out + (size_t)TOK * DM;

    const int SMEM_NN = (3 * 128 * RKS + 3 * 16 * KMS) * 4;   // 56832
    const int SMEM_NT = (3 * 128 * RKS * 2) * 4;              // 61440
    const int SMEM_TN = (3 * 16 * KMS * 2) * 4;               // 52224
    cudaFuncSetAttribute(k_qkv, cudaFuncAttributeMaxDynamicSharedMemorySize, SMEM_NN);
    cudaFuncSetAttribute(k_out, cudaFuncAttributeMaxDynamicSharedMemorySize, SMEM_NN);
    cudaFuncSetAttribute(k_nt,  cudaFuncAttributeMaxDynamicSharedMemorySize, SMEM_NT);
    cudaFuncSetAttribute(k_tn,  cudaFuncAttributeMaxDynamicSharedMemorySize, SMEM_TN);

    // pre-round weights + M_prev to tf32
    k_round<<<4096, 256>>>(Wq, Wk, Wv, Wo, Mprev);
    // fused q,k,v projections (x truncated, weights pre-rounded)
    k_qkv<<<dim3(6, 128), 256, SMEM_NN>>>(x, bq, bk, bv);
    // gate gamma
    k_gamma1<<<512, 256>>>(x, Wd);
    k_gamma2<<<1, 32>>>(bd, ts);
    // normalize q,k (rounded); layernorm v
    k_norm<<<TOK / 8, 256>>>(ln_g, ln_b);
    // surprise = v - k @ Mprev^T (in place, rounded)
    k_nt<<<dim3(2, 4, NBG), 256, SMEM_NT>>>(0);
    // Mnext = clip(gamma*Mprev + surprise^T @ k / NPG)
    k_tn<<<dim3(2, 2, NBG), 256, SMEM_TN>>>(Mprev, Mnext);
    // out_f = q @ Mnext^T (rounded)
    k_nt<<<dim3(2, 4, NBG), 256, SMEM_NT>>>(1);
    // out = out_f @ Wo + bo
    k_out<<<dim3(16, 128), 256, SMEM_NN>>>(bo, out);
}